// round 3
// baseline (speedup 1.0000x reference)
#include <cuda_runtime.h>

#define DD   128
#define NN   21845          // (4^8 - 1) / 3
#define NPOS 18
#define NDEP 46
#define CS6  5461           // level_start(7)

__host__ __device__ __forceinline__ int lvl_start(int l) {
    return ((1 << (2 * l)) - 1) / 3;
}

// persistent scratch (device globals: allocation-free)
__device__ float g_xz[NN * DD];            // x, then z in-place per level
__device__ float g_u[16384 * DD];          // level-6 child outputs
__device__ int   g_pos_perm[NN];
__device__ int   g_pos_off[NPOS + 1];
__device__ int   g_pos_tg[384], g_pos_tb[384];
__device__ int   g_pos_nt;
__device__ int   g_dep_perm[NN];
__device__ int   g_dep_off[7][NDEP + 1];
__device__ int   g_dep_tg[7][320], g_dep_tb[7][320];
__device__ int   g_dep_nt[7];
// grid barrier: cnt returns to 0 each use; gen is monotonic -> replay-safe
__device__ unsigned g_bar_cnt;
__device__ unsigned g_bar_gen;

__device__ __forceinline__ void gridbar(int nb) {
    __syncthreads();
    if (threadIdx.x == 0) {
        __threadfence();
        unsigned gen = *(volatile unsigned*)&g_bar_gen;
        if (atomicAdd(&g_bar_cnt, 1u) == (unsigned)nb - 1u) {
            atomicExch(&g_bar_cnt, 0u);
            __threadfence();
            atomicAdd(&g_bar_gen, 1u);
        } else {
            while (*(volatile unsigned*)&g_bar_gen == gen) __nanosleep(64);
        }
        __threadfence();
    }
    __syncthreads();
}

// ---------------------------------------------------------------------------
// Grouping (phase 0): block b in 0..7 builds table b (0=pos, 1..7=dep level b-1)
// ---------------------------------------------------------------------------
__device__ void do_group(const int* __restrict__ pos_ids,
                         const int* __restrict__ dep_ids, int b) {
    __shared__ int cnt[NDEP];
    __shared__ int off[NDEP + 1];
    int t = threadIdx.x, lane = t & 31;
    const int* ids; int n, ng, base, BM;
    int *perm, *goff, *tg, *tb, *nt_out;
    if (b == 0) {
        ids = pos_ids; n = NN; ng = NPOS; base = 0; BM = 64;
        perm = g_pos_perm; goff = g_pos_off;
        tg = g_pos_tg; tb = g_pos_tb; nt_out = &g_pos_nt;
    } else {
        int l = b - 1;
        base = lvl_start(l + 1); n = 1 << (2 * (l + 1)); ng = NDEP;
        BM = (l >= 5) ? 64 : 16;
        ids = dep_ids + base; perm = g_dep_perm + base; goff = g_dep_off[l];
        tg = g_dep_tg[l]; tb = g_dep_tb[l]; nt_out = &g_dep_nt[l];
    }
    if (t < ng) cnt[t] = 0;
    __syncthreads();
    for (int i0 = 0; i0 < n; i0 += blockDim.x) {
        int i = i0 + t; bool v = (i < n);
        unsigned act = __ballot_sync(0xffffffffu, v);
        if (v) {
            int id = ids[i];
            unsigned m = __match_any_sync(act, id);
            if (lane == __ffs(m) - 1) atomicAdd(&cnt[id], __popc(m));
        }
    }
    __syncthreads();
    if (t == 0) {
        int s = 0;
        for (int j = 0; j < ng; ++j) { off[j] = s; s += cnt[j]; }
        off[ng] = s;
        int nt = 0;
        for (int j = 0; j < ng; ++j) {
            int c = off[j + 1] - off[j];
            for (int k = 0; k < c; k += BM) { tg[nt] = j; tb[nt] = off[j] + k; ++nt; }
        }
        *nt_out = nt;
        for (int j = 0; j <= ng; ++j) goff[j] = off[j];
    }
    __syncthreads();
    if (t < ng) cnt[t] = off[t];   // cursors
    __syncthreads();
    for (int i0 = 0; i0 < n; i0 += blockDim.x) {
        int i = i0 + t; bool v = (i < n);
        unsigned act = __ballot_sync(0xffffffffu, v);
        if (v) {
            int id = ids[i];
            unsigned m = __match_any_sync(act, id);
            int leader = __ffs(m) - 1;
            int prior = __popc(m & ((1u << lane) - 1u));
            int bp = 0;
            if (lane == leader) bp = atomicAdd(&cnt[id], __popc(m));
            bp = __shfl_sync(act, bp, leader);
            perm[bp + prior] = base + i;   // global node index
        }
    }
}

// ---------------------------------------------------------------------------
// Big grouped GEMM tile: BM=64 x BN=128, K=128 in smem, 256 thr, 8x4 reg tile.
// mode 0: srcA=emb, store g_xz[node]
// mode 1: srcA=g_xz, store g_u[node-CS6]
// mode 2: srcA=g_xz, atomicMax into parent row of g_xz
// ---------------------------------------------------------------------------
#define SMEM_BIG ((16384 + 64 * 128) * 4)

__device__ __forceinline__ void big_phase(
    int mode, const float* __restrict__ Wsrc, const float* __restrict__ bias,
    const float* __restrict__ srcA, float* sW, float* sA,
    int nt, const int* __restrict__ tg, const int* __restrict__ tb,
    const int* __restrict__ off, const int* __restrict__ perm, int cs, int pb)
{
    __shared__ int sNode[64];
    int t = threadIdx.x;
    for (int tile = blockIdx.x; tile < nt; tile += gridDim.x) {
        __syncthreads();   // protect smem reuse across tiles/phases
        int j = tg[tile], b0 = tb[tile];
        int mc = off[j + 1] - b0; if (mc > 64) mc = 64;
        if (t < 64) sNode[t] = perm[b0 + min(t, mc - 1)];
        const float4* W4 = (const float4*)(Wsrc + (size_t)j * 16384);
        float4* sW4 = (float4*)sW;
#pragma unroll
        for (int i = 0; i < 16; ++i) sW4[t + 256 * i] = W4[t + 256 * i];
        __syncthreads();
        const float4* A4 = (const float4*)srcA;
#pragma unroll
        for (int i = 0; i < 8; ++i) {
            int idx = t + 256 * i; int r = idx >> 5, c = idx & 31;
            ((float4*)(sA + r * 128))[c] = A4[(size_t)sNode[r] * 32 + c];
        }
        __syncthreads();
        int tx = t & 31, ty = t >> 5;
        float acc[8][4];
#pragma unroll
        for (int i = 0; i < 8; ++i)
#pragma unroll
            for (int q = 0; q < 4; ++q) acc[i][q] = 0.f;
#pragma unroll 2
        for (int k4 = 0; k4 < 32; ++k4) {
            float4 a4[8], b4[4];
#pragma unroll
            for (int i = 0; i < 8; ++i)
                a4[i] = *(const float4*)&sA[(ty + 8 * i) * 128 + 4 * k4];
#pragma unroll
            for (int kk = 0; kk < 4; ++kk)
                b4[kk] = *(const float4*)&sW[(4 * k4 + kk) * 128 + 4 * tx];
#pragma unroll
            for (int i = 0; i < 8; ++i) {
                acc[i][0] += a4[i].x * b4[0].x; acc[i][1] += a4[i].x * b4[0].y;
                acc[i][2] += a4[i].x * b4[0].z; acc[i][3] += a4[i].x * b4[0].w;
                acc[i][0] += a4[i].y * b4[1].x; acc[i][1] += a4[i].y * b4[1].y;
                acc[i][2] += a4[i].y * b4[1].z; acc[i][3] += a4[i].y * b4[1].w;
                acc[i][0] += a4[i].z * b4[2].x; acc[i][1] += a4[i].z * b4[2].y;
                acc[i][2] += a4[i].z * b4[2].z; acc[i][3] += a4[i].z * b4[2].w;
                acc[i][0] += a4[i].w * b4[3].x; acc[i][1] += a4[i].w * b4[3].y;
                acc[i][2] += a4[i].w * b4[3].z; acc[i][3] += a4[i].w * b4[3].w;
            }
        }
        float4 bv = *(const float4*)&bias[j * 128 + 4 * tx];
#pragma unroll
        for (int i = 0; i < 8; ++i) {
            int node = sNode[ty + 8 * i];
            float ox = fmaxf(acc[i][0] + bv.x, 0.f);
            float oy = fmaxf(acc[i][1] + bv.y, 0.f);
            float oz = fmaxf(acc[i][2] + bv.z, 0.f);
            float ow = fmaxf(acc[i][3] + bv.w, 0.f);
            if (mode == 0) {
                float4 o; o.x = ox; o.y = oy; o.z = oz; o.w = ow;
                *(float4*)&g_xz[(size_t)node * 128 + 4 * tx] = o;
            } else if (mode == 1) {
                float4 o; o.x = ox; o.y = oy; o.z = oz; o.w = ow;
                *(float4*)&g_u[(size_t)(node - CS6) * 128 + 4 * tx] = o;
            } else {
                int parent = pb + ((node - cs) >> 2);
                int* zp = (int*)&g_xz[(size_t)parent * 128 + 4 * tx];
                // post-ReLU values >= 0: int ordering == float ordering
                atomicMax(zp + 0, __float_as_int(ox));
                atomicMax(zp + 1, __float_as_int(oy));
                atomicMax(zp + 2, __float_as_int(oz));
                atomicMax(zp + 3, __float_as_int(ow));
            }
        }
    }
}

// ---------------------------------------------------------------------------
// Narrow phase for small levels: item = (tile of 16 rows) x (32-col slice)
// 256 thr: r = t>>4 (16 rows), 16 threads x 2 cols each.
// ---------------------------------------------------------------------------
__device__ __forceinline__ void narrow_phase(
    int l, const float* __restrict__ Wsrc, const float* __restrict__ bias,
    float* sWn, float* sA2)
{
    __shared__ int sN[16];
    int t = threadIdx.x;
    int cs = lvl_start(l + 1), pb = lvl_start(l);
    int nt = g_dep_nt[l];
    int items = nt * 4;
    const int* tg = g_dep_tg[l];
    const int* tb = g_dep_tb[l];
    const int* off = g_dep_off[l];
    for (int item = blockIdx.x; item < items; item += gridDim.x) {
        __syncthreads();
        int tile = item >> 2, slice = item & 3, c0 = slice * 32;
        int j = tg[tile], b0 = tb[tile];
        int mc = off[j + 1] - b0; if (mc > 16) mc = 16;
        if (t < 16) sN[t] = g_dep_perm[cs + b0 + min(t, mc - 1)];
        // W slice: 128 rows x 32 cols -> sWn[k*36 + c]
#pragma unroll
        for (int i = 0; i < 4; ++i) {
            int idx = t + 256 * i; int k = idx >> 3, c4 = idx & 7;
            *(float4*)&sWn[k * 36 + 4 * c4] =
                *(const float4*)&Wsrc[(size_t)j * 16384 + k * 128 + c0 + 4 * c4];
        }
        __syncthreads();
        const float4* Z4 = (const float4*)g_xz;
#pragma unroll
        for (int i = 0; i < 2; ++i) {
            int idx = t + 256 * i; int r = idx >> 5, c = idx & 31;
            ((float4*)(sA2 + r * 128))[c] = Z4[(size_t)sN[r] * 32 + c];
        }
        __syncthreads();
        int r = t >> 4, x16 = t & 15;
        float a0 = 0.f, a1 = 0.f;
#pragma unroll 4
        for (int k = 0; k < 128; ++k) {
            float a = sA2[r * 128 + k];
            float2 w = *(const float2*)&sWn[k * 36 + 2 * x16];
            a0 += a * w.x; a1 += a * w.y;
        }
        int node = sN[r];
        int parent = pb + ((node - cs) >> 2);
        int col = c0 + 2 * x16;
        float2 bv = *(const float2*)&bias[j * 128 + col];
        int* zp = (int*)&g_xz[(size_t)parent * 128 + col];
        atomicMax(zp + 0, __float_as_int(fmaxf(a0 + bv.x, 0.f)));
        atomicMax(zp + 1, __float_as_int(fmaxf(a1 + bv.y, 0.f)));
    }
}

// ---------------------------------------------------------------------------
// The single persistent mega-kernel
// ---------------------------------------------------------------------------
__global__ __launch_bounds__(256, 2)
void mega_kernel(const float* __restrict__ emb,
                 const int* __restrict__ pos_ids,
                 const int* __restrict__ dep_ids,
                 const float* __restrict__ pos_W, const float* __restrict__ pos_b,
                 const float* __restrict__ dep_W, const float* __restrict__ dep_b,
                 float* __restrict__ out)
{
    extern __shared__ float sm[];
    float* sW = sm;            // 16384 floats
    float* sA = sm + 16384;    // 8192 floats
    int nb = gridDim.x;
    int t = threadIdx.x;

    // phase 0: grouping
    if (blockIdx.x < 8) do_group(pos_ids, dep_ids, blockIdx.x);
    gridbar(nb);

    // phase 1: pos GEMM (all nodes)
    big_phase(0, pos_W, pos_b, emb, sW, sA,
              g_pos_nt, g_pos_tg, g_pos_tb, g_pos_off, g_pos_perm, 0, 0);
    gridbar(nb);

    // phase 2: dep level 6 GEMM -> g_u
    big_phase(1, dep_W, dep_b, g_xz, sW, sA,
              g_dep_nt[6], g_dep_tg[6], g_dep_tb[6], g_dep_off[6],
              g_dep_perm + CS6, CS6, lvl_start(6));
    gridbar(nb);

    // phase 3: reduce6  z[p] = max(x[p], max4 u)
    {
        const int pb = lvl_start(6);
        int tot = 4096 * 32;
        const float4* u = (const float4*)g_u;
        for (int idx = blockIdx.x * 256 + t; idx < tot; idx += nb * 256) {
            int p = idx >> 5, c = idx & 31;
            float4 a = u[(size_t)(4 * p + 0) * 32 + c];
            float4 b = u[(size_t)(4 * p + 1) * 32 + c];
            float4 d = u[(size_t)(4 * p + 2) * 32 + c];
            float4 e = u[(size_t)(4 * p + 3) * 32 + c];
            float4* z = (float4*)&g_xz[(size_t)(pb + p) * 128];
            float4 x = z[c];
            x.x = fmaxf(x.x, fmaxf(fmaxf(a.x, b.x), fmaxf(d.x, e.x)));
            x.y = fmaxf(x.y, fmaxf(fmaxf(a.y, b.y), fmaxf(d.y, e.y)));
            x.z = fmaxf(x.z, fmaxf(fmaxf(a.z, b.z), fmaxf(d.z, e.z)));
            x.w = fmaxf(x.w, fmaxf(fmaxf(a.w, b.w), fmaxf(d.w, e.w)));
            z[c] = x;
        }
    }
    gridbar(nb);

    // phase 4: dep level 5 (4096 children) big tiles + atomicMax epilogue
    big_phase(2, dep_W, dep_b, g_xz, sW, sA,
              g_dep_nt[5], g_dep_tg[5], g_dep_tb[5], g_dep_off[5],
              g_dep_perm + lvl_start(6), lvl_start(6), lvl_start(5));
    gridbar(nb);

    // phases 5..9: dep levels 4..0 narrow
    for (int l = 4; l >= 0; --l) {
        narrow_phase(l, dep_W, dep_b, sW, sA);
        gridbar(nb);
    }

    // final: write root row to output
    if (blockIdx.x == 0 && t < 128) out[t] = g_xz[t];
}

// ---------------------------------------------------------------------------
extern "C" void kernel_launch(void* const* d_in, const int* in_sizes, int n_in,
                              void* d_out, int out_size) {
    const float* emb     = (const float*)d_in[0];
    const int*   pos_ids = (const int*)d_in[1];
    const int*   dep_ids = (const int*)d_in[2];
    const float* pos_W   = (const float*)d_in[3];
    const float* pos_b   = (const float*)d_in[4];
    const float* dep_W   = (const float*)d_in[5];
    const float* dep_b   = (const float*)d_in[6];

    cudaFuncSetAttribute(mega_kernel, cudaFuncAttributeMaxDynamicSharedMemorySize,
                         SMEM_BIG);
    int dev = 0, nsm = 0, occ = 0;
    cudaGetDevice(&dev);
    cudaDeviceGetAttribute(&nsm, cudaDevAttrMultiProcessorCount, dev);
    cudaOccupancyMaxActiveBlocksPerMultiprocessor(&occ, mega_kernel, 256, SMEM_BIG);
    if (occ < 1) occ = 1;
    int grid = nsm * occ;
    if (grid > 512) grid = 512;

    mega_kernel<<<grid, 256, SMEM_BIG>>>(emb, pos_ids, dep_ids,
                                         pos_W, pos_b, dep_W, dep_b,
                                         (float*)d_out);
}

// round 4
// speedup vs baseline: 1.2817x; 1.2817x over previous
#include <cuda_runtime.h>

#define DD   128
#define NN   21845          // (4^8 - 1) / 3
#define NPOS 18
#define NDEP 46
#define CS6  5461           // level_start(7)

__host__ __device__ __forceinline__ int lvl_start(int l) {
    return ((1 << (2 * l)) - 1) / 3;
}

typedef unsigned long long ull;

// packed f32x2 helpers (FFMA2: only reachable via PTX fma.rn.f32x2)
__device__ __forceinline__ ull rep2(float s) {
    ull r; asm("mov.b64 %0, {%1, %1};" : "=l"(r) : "f"(s)); return r;
}
__device__ __forceinline__ void fma2(ull& acc, ull a, ull b) {
    asm("fma.rn.f32x2 %0, %1, %2, %0;" : "+l"(acc) : "l"(a), "l"(b));
}
__device__ __forceinline__ void unpack2(ull v, float& lo, float& hi) {
    asm("mov.b64 {%0, %1}, %2;" : "=f"(lo), "=f"(hi) : "l"(v));
}

// persistent scratch (device globals: allocation-free)
__device__ float g_xz[NN * DD];            // x, then z in-place per level
__device__ int   g_pos_perm[NN];
__device__ int   g_pos_off[NPOS + 1];
__device__ int   g_pos_tg[384], g_pos_tb[384];
__device__ int   g_pos_nt;
__device__ int   g_dep_perm[NN];
__device__ int   g_dep_off[7][NDEP + 1];
__device__ int   g_dep_tg[7][320], g_dep_tb[7][320];
__device__ int   g_dep_nt[7];
// grid barrier (narrow kernel): cnt returns to 0; gen monotonic -> replay-safe
__device__ unsigned g_bar_cnt;
__device__ unsigned g_bar_gen;

__device__ __forceinline__ void gridbar(int nb) {
    __syncthreads();
    if (threadIdx.x == 0) {
        __threadfence();
        unsigned gen = *(volatile unsigned*)&g_bar_gen;
        if (atomicAdd(&g_bar_cnt, 1u) == (unsigned)nb - 1u) {
            atomicExch(&g_bar_cnt, 0u);
            __threadfence();
            atomicAdd(&g_bar_gen, 1u);
        } else {
            while (*(volatile unsigned*)&g_bar_gen == gen) __nanosleep(64);
        }
        __threadfence();
    }
    __syncthreads();
}

// ---------------------------------------------------------------------------
// Grouping: block 0 = pos (1024 thr over NN), blocks 1..7 = dep level b-1
// ---------------------------------------------------------------------------
__global__ void group_kernel(const int* __restrict__ pos_ids,
                             const int* __restrict__ dep_ids) {
    __shared__ int cnt[NDEP];
    __shared__ int off[NDEP + 1];
    int t = threadIdx.x, lane = t & 31;
    const int* ids; int n, ng, base, BM;
    int *perm, *goff, *tg, *tb, *nt_out;
    if (blockIdx.x == 0) {
        ids = pos_ids; n = NN; ng = NPOS; base = 0; BM = 64;
        perm = g_pos_perm; goff = g_pos_off;
        tg = g_pos_tg; tb = g_pos_tb; nt_out = &g_pos_nt;
    } else {
        int l = blockIdx.x - 1;
        base = lvl_start(l + 1); n = 1 << (2 * (l + 1)); ng = NDEP;
        BM = (l >= 5) ? 64 : 16;
        ids = dep_ids + base; perm = g_dep_perm + base; goff = g_dep_off[l];
        tg = g_dep_tg[l]; tb = g_dep_tb[l]; nt_out = &g_dep_nt[l];
    }
    if (t < ng) cnt[t] = 0;
    __syncthreads();
    for (int i0 = 0; i0 < n; i0 += blockDim.x) {
        int i = i0 + t; bool v = (i < n);
        unsigned act = __ballot_sync(0xffffffffu, v);
        if (v) {
            int id = ids[i];
            unsigned m = __match_any_sync(act, id);
            if (lane == __ffs(m) - 1) atomicAdd(&cnt[id], __popc(m));
        }
    }
    __syncthreads();
    if (t == 0) {
        int s = 0;
        for (int j = 0; j < ng; ++j) { off[j] = s; s += cnt[j]; }
        off[ng] = s;
        int nt = 0;
        for (int j = 0; j < ng; ++j) {
            int c = off[j + 1] - off[j];
            for (int k = 0; k < c; k += BM) { tg[nt] = j; tb[nt] = off[j] + k; ++nt; }
        }
        *nt_out = nt;
        for (int j = 0; j <= ng; ++j) goff[j] = off[j];
    }
    __syncthreads();
    if (t < ng) cnt[t] = off[t];   // cursors
    __syncthreads();
    for (int i0 = 0; i0 < n; i0 += blockDim.x) {
        int i = i0 + t; bool v = (i < n);
        unsigned act = __ballot_sync(0xffffffffu, v);
        if (v) {
            int id = ids[i];
            unsigned m = __match_any_sync(act, id);
            int leader = __ffs(m) - 1;
            int prior = __popc(m & ((1u << lane) - 1u));
            int bp = 0;
            if (lane == leader) bp = atomicAdd(&cnt[id], __popc(m));
            bp = __shfl_sync(act, bp, leader);
            perm[bp + prior] = base + i;   // global node index
        }
    }
}

// ---------------------------------------------------------------------------
// Big grouped GEMM: BM=64 x BN=128, K=128 in smem, 256 thr.
// FFMA2 core: col-pair accumulators, {a,a} replicated via mov.b64 (ALU pipe).
// mode 0: srcA=emb, plain store to g_xz[node]
// mode 2: srcA=g_xz, atomicMax into parent row of g_xz
// ---------------------------------------------------------------------------
#define SMEM_BIG ((16384 + 64 * 128) * 4)

__global__ __launch_bounds__(256, 2)
void gemm_big(int mode, const float* __restrict__ Wsrc,
              const float* __restrict__ bias, const float* __restrict__ srcA,
              const int* __restrict__ nt_p, const int* __restrict__ tg,
              const int* __restrict__ tb, const int* __restrict__ off,
              const int* __restrict__ perm, int cs, int pb)
{
    int tile = blockIdx.x;
    if (tile >= *nt_p) return;
    extern __shared__ float sm[];
    float* sW = sm;            // 128x128
    float* sA = sm + 16384;    // 64x128
    __shared__ int sNode[64];
    int t = threadIdx.x;
    int j = tg[tile], b0 = tb[tile];
    int mc = off[j + 1] - b0; if (mc > 64) mc = 64;
    if (t < 64) sNode[t] = perm[b0 + min(t, mc - 1)];
    const float4* W4 = (const float4*)(Wsrc + (size_t)j * 16384);
    float4* sW4 = (float4*)sW;
#pragma unroll
    for (int i = 0; i < 16; ++i) sW4[t + 256 * i] = W4[t + 256 * i];
    __syncthreads();
    const float4* A4 = (const float4*)srcA;
#pragma unroll
    for (int i = 0; i < 8; ++i) {
        int idx = t + 256 * i; int r = idx >> 5, c = idx & 31;
        ((float4*)(sA + r * 128))[c] = A4[(size_t)sNode[r] * 32 + c];
    }
    __syncthreads();
    int tx = t & 31, ty = t >> 5;
    ull acc2[8][2];
#pragma unroll
    for (int i = 0; i < 8; ++i) { acc2[i][0] = 0ull; acc2[i][1] = 0ull; }
#pragma unroll 2
    for (int k4 = 0; k4 < 32; ++k4) {
        float4 a4[8]; ulonglong2 b2[4];
#pragma unroll
        for (int i = 0; i < 8; ++i)
            a4[i] = *(const float4*)&sA[(ty + 8 * i) * 128 + 4 * k4];
#pragma unroll
        for (int kk = 0; kk < 4; ++kk)
            b2[kk] = *(const ulonglong2*)&sW[(4 * k4 + kk) * 128 + 4 * tx];
#pragma unroll
        for (int i = 0; i < 8; ++i) {
            ull a;
            a = rep2(a4[i].x); fma2(acc2[i][0], a, b2[0].x); fma2(acc2[i][1], a, b2[0].y);
            a = rep2(a4[i].y); fma2(acc2[i][0], a, b2[1].x); fma2(acc2[i][1], a, b2[1].y);
            a = rep2(a4[i].z); fma2(acc2[i][0], a, b2[2].x); fma2(acc2[i][1], a, b2[2].y);
            a = rep2(a4[i].w); fma2(acc2[i][0], a, b2[3].x); fma2(acc2[i][1], a, b2[3].y);
        }
    }
    float4 bv = *(const float4*)&bias[j * 128 + 4 * tx];
#pragma unroll
    for (int i = 0; i < 8; ++i) {
        int node = sNode[ty + 8 * i];
        float v0, v1, v2, v3;
        unpack2(acc2[i][0], v0, v1);
        unpack2(acc2[i][1], v2, v3);
        float ox = fmaxf(v0 + bv.x, 0.f);
        float oy = fmaxf(v1 + bv.y, 0.f);
        float oz = fmaxf(v2 + bv.z, 0.f);
        float ow = fmaxf(v3 + bv.w, 0.f);
        if (mode == 0) {
            float4 o; o.x = ox; o.y = oy; o.z = oz; o.w = ow;
            *(float4*)&g_xz[(size_t)node * 128 + 4 * tx] = o;
        } else {
            int parent = pb + ((node - cs) >> 2);
            int* zp = (int*)&g_xz[(size_t)parent * 128 + 4 * tx];
            // post-ReLU values >= 0: int ordering == float ordering
            atomicMax(zp + 0, __float_as_int(ox));
            atomicMax(zp + 1, __float_as_int(oy));
            atomicMax(zp + 2, __float_as_int(oz));
            atomicMax(zp + 3, __float_as_int(ow));
        }
    }
}

// ---------------------------------------------------------------------------
// Narrow persistent kernel: levels 4..0, internal grid barrier between levels.
// item = (16-row tile) x (32-col slice); 256 thr: 16 rows x 16 thr x 2 cols.
// ---------------------------------------------------------------------------
__global__ __launch_bounds__(256, 2)
void narrow_all(const float* __restrict__ Wsrc, const float* __restrict__ bias)
{
    __shared__ __align__(16) float sWn[128 * 36];
    __shared__ __align__(16) float sA2[16 * 128];
    __shared__ int sN[16];
    int t = threadIdx.x;
    int nb = gridDim.x;
    for (int l = 4; l >= 0; --l) {
        int cs = lvl_start(l + 1), pb = lvl_start(l);
        int nt = g_dep_nt[l];
        int items = nt * 4;
        const int* tg = g_dep_tg[l];
        const int* tb = g_dep_tb[l];
        const int* off = g_dep_off[l];
        for (int item = blockIdx.x; item < items; item += nb) {
            __syncthreads();
            int tile = item >> 2, slice = item & 3, c0 = slice * 32;
            int j = tg[tile], b0 = tb[tile];
            int mc = off[j + 1] - b0; if (mc > 16) mc = 16;
            if (t < 16) sN[t] = g_dep_perm[cs + b0 + min(t, mc - 1)];
#pragma unroll
            for (int i = 0; i < 4; ++i) {
                int idx = t + 256 * i; int k = idx >> 3, c4 = idx & 7;
                *(float4*)&sWn[k * 36 + 4 * c4] =
                    *(const float4*)&Wsrc[(size_t)j * 16384 + k * 128 + c0 + 4 * c4];
            }
            __syncthreads();
            const float4* Z4 = (const float4*)g_xz;
#pragma unroll
            for (int i = 0; i < 2; ++i) {
                int idx = t + 256 * i; int r = idx >> 5, c = idx & 31;
                ((float4*)(sA2 + r * 128))[c] = Z4[(size_t)sN[r] * 32 + c];
            }
            __syncthreads();
            int r = t >> 4, x16 = t & 15;
            ull acc = 0ull;
#pragma unroll 4
            for (int k = 0; k < 128; ++k) {
                ull a = rep2(sA2[r * 128 + k]);
                ull w = *(const ull*)&sWn[k * 36 + 2 * x16];
                fma2(acc, a, w);
            }
            int node = sN[r];
            int parent = pb + ((node - cs) >> 2);
            int col = c0 + 2 * x16;
            float2 bv = *(const float2*)&bias[j * 128 + col];
            float a0, a1; unpack2(acc, a0, a1);
            int* zp = (int*)&g_xz[(size_t)parent * 128 + col];
            atomicMax(zp + 0, __float_as_int(fmaxf(a0 + bv.x, 0.f)));
            atomicMax(zp + 1, __float_as_int(fmaxf(a1 + bv.y, 0.f)));
        }
        gridbar(nb);
    }
}

__global__ void copy_out_kernel(float* __restrict__ out) {
    out[threadIdx.x] = g_xz[threadIdx.x];   // root node 0
}

// ---------------------------------------------------------------------------
extern "C" void kernel_launch(void* const* d_in, const int* in_sizes, int n_in,
                              void* d_out, int out_size) {
    const float* emb     = (const float*)d_in[0];
    const int*   pos_ids = (const int*)d_in[1];
    const int*   dep_ids = (const int*)d_in[2];
    const float* pos_W   = (const float*)d_in[3];
    const float* pos_b   = (const float*)d_in[4];
    const float* dep_W   = (const float*)d_in[5];
    const float* dep_b   = (const float*)d_in[6];

    cudaFuncSetAttribute(gemm_big, cudaFuncAttributeMaxDynamicSharedMemorySize,
                         SMEM_BIG);

    // device-global addresses for table pointers
    int *d_pos_nt, *d_pos_tg, *d_pos_tb, *d_pos_off, *d_pos_perm;
    int *d_dep_nt, *d_dep_tg, *d_dep_tb, *d_dep_off, *d_dep_perm;
    cudaGetSymbolAddress((void**)&d_pos_nt,   g_pos_nt);
    cudaGetSymbolAddress((void**)&d_pos_tg,   g_pos_tg);
    cudaGetSymbolAddress((void**)&d_pos_tb,   g_pos_tb);
    cudaGetSymbolAddress((void**)&d_pos_off,  g_pos_off);
    cudaGetSymbolAddress((void**)&d_pos_perm, g_pos_perm);
    cudaGetSymbolAddress((void**)&d_dep_nt,   g_dep_nt);
    cudaGetSymbolAddress((void**)&d_dep_tg,   g_dep_tg);
    cudaGetSymbolAddress((void**)&d_dep_tb,   g_dep_tb);
    cudaGetSymbolAddress((void**)&d_dep_off,  g_dep_off);
    cudaGetSymbolAddress((void**)&d_dep_perm, g_dep_perm);
    float* d_xz;
    cudaGetSymbolAddress((void**)&d_xz, g_xz);

    group_kernel<<<8, 1024>>>(pos_ids, dep_ids);

    // pos: all NN nodes, plain store
    gemm_big<<<360, 256, SMEM_BIG>>>(0, pos_W, pos_b, emb,
        d_pos_nt, d_pos_tg, d_pos_tb, d_pos_off, d_pos_perm, 0, 0);

    // dep level 6: 16384 children, atomicMax epilogue into level-6 parents
    gemm_big<<<302, 256, SMEM_BIG>>>(2, dep_W, dep_b, d_xz,
        d_dep_nt + 6, d_dep_tg + 6 * 320, d_dep_tb + 6 * 320,
        d_dep_off + 6 * (NDEP + 1), d_dep_perm + CS6, CS6, lvl_start(6));

    // dep level 5: 4096 children
    gemm_big<<<110, 256, SMEM_BIG>>>(2, dep_W, dep_b, d_xz,
        d_dep_nt + 5, d_dep_tg + 5 * 320, d_dep_tb + 5 * 320,
        d_dep_off + 5 * (NDEP + 1), d_dep_perm + lvl_start(6),
        lvl_start(6), lvl_start(5));

    // levels 4..0 in one persistent kernel with internal grid barriers
    int dev = 0, nsm = 0, occ = 0;
    cudaGetDevice(&dev);
    cudaDeviceGetAttribute(&nsm, cudaDevAttrMultiProcessorCount, dev);
    cudaOccupancyMaxActiveBlocksPerMultiprocessor(&occ, narrow_all, 256, 0);
    if (occ < 1) occ = 1;
    int grid = nsm * (occ < 2 ? occ : 2);
    narrow_all<<<grid, 256>>>(dep_W, dep_b);

    copy_out_kernel<<<1, 128>>>((float*)d_out);
}